// round 4
// baseline (speedup 1.0000x reference)
#include <cuda_runtime.h>
#include <math.h>

#define N_NODES 100000
#define D 128
#define MAX_E 1600000
#define GEMM_ROWS 64
#define BK 32

// ---------------- scratch (static device globals; no runtime alloc) ----------
__device__ __align__(16) int   g_deg[N_NODES];
__device__ __align__(16) int   g_rowptr[N_NODES + 1];
__device__ __align__(16) int   g_cursor[N_NODES];
__device__ __align__(16) int   g_col[MAX_E];
__device__ __align__(16) float g_agg[(size_t)N_NODES * D];
__device__ __align__(16) float g_h[(size_t)N_NODES * D];
__device__ int g_not64;   // 1 => edge_index is int32, 0 => int64

// ---------------- dtype probe -------------------------------------------------
// If the int64 interpretation of the first entries is all in-range, dtype is
// int64. For int32 data the paired high words are independent node ids,
// virtually never all zero across 4096 entries.
__global__ void k_probe(const void* __restrict__ ei, int E) {
    int i = blockIdx.x * blockDim.x + threadIdx.x;
    if (i == 0 && blockIdx.x == 0) { /* flag already zeroed in k_zero_deg */ }
    int n = E < 4096 ? E : 4096;
    if (i < n) {
        long long v = ((const long long*)ei)[i];
        if (v < 0 || v >= N_NODES) atomicExch(&g_not64, 1);
    }
}

// ---------------- CSR build ---------------------------------------------------
__global__ void k_zero_deg() {
    int i = blockIdx.x * blockDim.x + threadIdx.x;
    if (i < N_NODES) g_deg[i] = 0;
    if (i == 0) g_not64 = 0;
}

__device__ __forceinline__ int load_idx(const void* ei, long long pos) {
    if (g_not64) return ((const int*)ei)[pos];
    return (int)((const long long*)ei)[pos];
}

__global__ void k_hist(const void* __restrict__ ei, int E) {
    int i = blockIdx.x * blockDim.x + threadIdx.x;
    if (i < E) {
        int d = load_idx(ei, (long long)E + i);   // dst row
        if ((unsigned)d < N_NODES) atomicAdd(&g_deg[d], 1);
    }
}

// single-block 1024-thread chunked Hillis-Steele exclusive scan
__global__ void k_scan() {
    __shared__ int buf[1024];
    int carry = 0;
    for (int base = 0; base < N_NODES; base += 1024) {
        int i = base + threadIdx.x;
        int v = (i < N_NODES) ? g_deg[i] : 0;
        buf[threadIdx.x] = v;
        __syncthreads();
        int xv = v;
        for (int off = 1; off < 1024; off <<= 1) {
            int t = (threadIdx.x >= off) ? buf[threadIdx.x - off] : 0;
            __syncthreads();
            xv += t;
            buf[threadIdx.x] = xv;
            __syncthreads();
        }
        if (i < N_NODES) {
            int excl = carry + xv - v;
            g_rowptr[i] = excl;
            g_cursor[i] = excl;
        }
        int tot = buf[1023];
        __syncthreads();
        carry += tot;
    }
    if (threadIdx.x == 0) g_rowptr[N_NODES] = carry;
}

__global__ void k_fill(const void* __restrict__ ei, int E) {
    int i = blockIdx.x * blockDim.x + threadIdx.x;
    if (i < E) {
        int d = load_idx(ei, (long long)E + i);
        int s = load_idx(ei, i);
        if ((unsigned)d < N_NODES && (unsigned)s < N_NODES) {
            int pos = atomicAdd(&g_cursor[d], 1);
            if (pos < MAX_E) g_col[pos] = s;
        }
    }
}

// ---------------- aggregation: one warp per node, mean of neighbor rows -------
// layer==0: source = X param. layer==1: source = g_h (device global).
__global__ void k_agg(const float* __restrict__ X, int layer) {
    int gw = (blockIdx.x * blockDim.x + threadIdx.x) >> 5;
    int lane = threadIdx.x & 31;
    if (gw >= N_NODES) return;
    int s = g_rowptr[gw];
    int e = g_rowptr[gw + 1];
    const float4* Xv = (layer == 0) ? (const float4*)X : (const float4*)g_h;
    float4 acc = make_float4(0.f, 0.f, 0.f, 0.f);
    for (int j = s; j < e; j++) {
        int nb = g_col[j];
        float4 v = Xv[(size_t)nb * 32 + lane];
        acc.x += v.x; acc.y += v.y; acc.z += v.z; acc.w += v.w;
    }
    float inv = 1.0f / fmaxf((float)(e - s), 1.0f);
    acc.x *= inv; acc.y *= inv; acc.z *= inv; acc.w *= inv;
    ((float4*)g_agg)[(size_t)gw * 32 + lane] = acc;
}

// ---------------- fused GEMM: out = agg@Wl + self@Wr + b, l2norm (+relu) -----
// block: 256 threads -> 64 rows x 128 cols tile; thread: 4 rows x 8 cols.
// K=256 (agg stacked with self) processed in 8 chunks of 32. Static smem only.
// layer==0: self = X, dst = g_h, relu on. layer==1: self = g_h, dst = OUT.
__global__ void __launch_bounds__(256)
k_gemm(const float* __restrict__ X,
       const float* __restrict__ Wl, const float* __restrict__ Wr,
       const float* __restrict__ b, float* __restrict__ OUT, int layer) {
    __shared__ float Ws[BK][128];     // 16 KB  [kk][col]
    __shared__ float As[BK][68];      // 8.7 KB [kk][row] (pad 68 keeps 16B align)
    int tid = threadIdx.x;
    int row0 = blockIdx.x * GEMM_ROWS;

    const float* self = (layer == 0) ? X : (const float*)g_h;
    float* dstbuf = (layer == 0) ? (float*)g_h : OUT;

    int tx = tid & 15;   // 16 col-groups x 8 cols = 128
    int ty = tid >> 4;   // 16 row-groups x 4 rows = 64

    float acc[4][8];
#pragma unroll
    for (int r = 0; r < 4; r++)
#pragma unroll
        for (int c = 0; c < 8; c++) acc[r][c] = 0.f;

    for (int ch = 0; ch < 8; ch++) {
        int k0 = ch * BK;
        // load W chunk: 32x128 floats, float4 per iter, coalesced
#pragma unroll
        for (int i = tid * 4; i < BK * 128; i += 1024) {
            int kk = i >> 7;
            int cc = i & 127;
            int kg = k0 + kk;
            const float* wsrc = (kg < 128) ? (Wl + (size_t)kg * 128 + cc)
                                           : (Wr + (size_t)(kg - 128) * 128 + cc);
            *(float4*)&Ws[kk][cc] = *(const float4*)wsrc;
        }
        // load A chunk transposed: As[kk][r] = src[row0+r][k0+kk]
#pragma unroll
        for (int i = tid; i < GEMM_ROWS * BK; i += 256) {
            int r = i >> 5;
            int kk = i & 31;
            int grow = row0 + r;
            int kg = k0 + kk;
            float v = 0.f;
            if (grow < N_NODES)
                v = (kg < 128) ? g_agg[(size_t)grow * 128 + kg]
                               : self[(size_t)grow * 128 + (kg - 128)];
            As[kk][r] = v;
        }
        __syncthreads();

#pragma unroll
        for (int kk = 0; kk < BK; kk++) {
            float4 a  = *(const float4*)&As[kk][ty << 2];
            float4 w0 = *(const float4*)&Ws[kk][tx << 3];
            float4 w1 = *(const float4*)&Ws[kk][(tx << 3) + 4];
            float av[4] = {a.x, a.y, a.z, a.w};
            float wv[8] = {w0.x, w0.y, w0.z, w0.w, w1.x, w1.y, w1.z, w1.w};
#pragma unroll
            for (int r = 0; r < 4; r++)
#pragma unroll
                for (int c = 0; c < 8; c++)
                    acc[r][c] = fmaf(av[r], wv[c], acc[r][c]);
        }
        __syncthreads();
    }

    // epilogue: bias, l2-normalize across 128 cols (16 tx lanes), optional relu
    float bias[8];
#pragma unroll
    for (int c = 0; c < 8; c++) bias[c] = b[(tx << 3) + c];

#pragma unroll
    for (int r = 0; r < 4; r++) {
        float s = 0.f;
#pragma unroll
        for (int c = 0; c < 8; c++) {
            acc[r][c] += bias[c];
            s = fmaf(acc[r][c], acc[r][c], s);
        }
#pragma unroll
        for (int m = 1; m < 16; m <<= 1)
            s += __shfl_xor_sync(0xffffffffu, s, m);
        float inv = 1.0f / fmaxf(sqrtf(s), 1e-12f);
        int grow = row0 + (ty << 2) + r;
        if (grow < N_NODES) {
            float ov[8];
#pragma unroll
            for (int c = 0; c < 8; c++) {
                float o = acc[r][c] * inv;
                if (layer == 0) o = fmaxf(o, 0.f);
                ov[c] = o;
            }
            float* dstp = dstbuf + (size_t)grow * 128 + (tx << 3);
            *(float4*)dstp       = make_float4(ov[0], ov[1], ov[2], ov[3]);
            *(float4*)(dstp + 4) = make_float4(ov[4], ov[5], ov[6], ov[7]);
        }
    }
}

// ---------------- launch ------------------------------------------------------
extern "C" void kernel_launch(void* const* d_in, const int* in_sizes, int n_in,
                              void* d_out, int out_size) {
    const float* x   = (const float*)d_in[0];
    const void*  ei  = d_in[1];
    const float* W1l = (const float*)d_in[2];
    const float* b1  = (const float*)d_in[3];
    const float* W1r = (const float*)d_in[4];
    const float* W2l = (const float*)d_in[5];
    const float* b2  = (const float*)d_in[6];
    const float* W2r = (const float*)d_in[7];

    int E = in_sizes[1] / 2;
    float* out = (float*)d_out;

    int eb = (E + 255) / 256;

    // CSR build (per launch; deterministic work)
    k_zero_deg<<<(N_NODES + 255) / 256, 256>>>();
    k_probe<<<16, 256>>>(ei, E);
    k_hist<<<eb, 256>>>(ei, E);
    k_scan<<<1, 1024>>>();
    k_fill<<<eb, 256>>>(ei, E);

    int aggBlocks  = (N_NODES * 32 + 255) / 256;
    int gemmBlocks = (N_NODES + GEMM_ROWS - 1) / GEMM_ROWS;

    // layer 1: agg(x) -> gemm -> g_h (normalize + relu)
    k_agg<<<aggBlocks, 256>>>(x, 0);
    k_gemm<<<gemmBlocks, 256>>>(x, W1l, W1r, b1, out, 0);

    // layer 2: agg(g_h) -> gemm -> out (normalize)
    k_agg<<<aggBlocks, 256>>>(x, 1);
    k_gemm<<<gemmBlocks, 256>>>(x, W2l, W2r, b2, out, 1);
}

// round 5
// speedup vs baseline: 2.9117x; 2.9117x over previous
#include <cuda_runtime.h>
#include <math.h>
#include <stdint.h>

#define N_NODES 100000
#define D 128
#define MAX_E 1600000
#define BM 128

// ---------------- scratch (static device globals; no runtime alloc) ----------
__device__ __align__(16) int   g_deg[N_NODES];
__device__ __align__(16) int   g_rowptr[N_NODES];
__device__ __align__(16) int   g_cursor[N_NODES];
__device__ __align__(16) int   g_col[MAX_E];
__device__ __align__(16) float g_agg[(size_t)N_NODES * D];
__device__ __align__(16) float g_h[(size_t)N_NODES * D];
__device__ int g_not64;   // 1 => edge_index is int32, 0 => int64
__device__ int g_total;   // segment allocator

// ---------------- dtype probe -------------------------------------------------
__global__ void k_probe(const void* __restrict__ ei, int E) {
    int i = blockIdx.x * blockDim.x + threadIdx.x;
    int n = E < 4096 ? E : 4096;
    if (i < n) {
        long long v = ((const long long*)ei)[i];
        if (v < 0 || v >= N_NODES) atomicExch(&g_not64, 1);
    }
}

// ---------------- CSR build ---------------------------------------------------
__global__ void k_zero_deg() {
    int i = blockIdx.x * blockDim.x + threadIdx.x;
    if (i < N_NODES) g_deg[i] = 0;
    if (i == 0) { g_not64 = 0; g_total = 0; }
}

__device__ __forceinline__ int load_idx(const void* ei, long long pos) {
    if (g_not64) return ((const int*)ei)[pos];
    return (int)((const long long*)ei)[pos];
}

__global__ void k_hist(const void* __restrict__ ei, int E) {
    int i = blockIdx.x * blockDim.x + threadIdx.x;
    if (i < E) {
        int d = load_idx(ei, (long long)E + i);   // dst row
        if ((unsigned)d < N_NODES) atomicAdd(&g_deg[d], 1);
    }
}

// segment offsets without a scan: order-free unique base per node
__global__ void k_offsets() {
    int i = blockIdx.x * blockDim.x + threadIdx.x;
    if (i < N_NODES) {
        int d = g_deg[i];
        int base = atomicAdd(&g_total, d);
        g_rowptr[i] = base;
        g_cursor[i] = base;
    }
}

__global__ void k_fill(const void* __restrict__ ei, int E) {
    int i = blockIdx.x * blockDim.x + threadIdx.x;
    if (i < E) {
        int d = load_idx(ei, (long long)E + i);
        int s = load_idx(ei, i);
        if ((unsigned)d < N_NODES && (unsigned)s < N_NODES) {
            int pos = atomicAdd(&g_cursor[d], 1);
            if (pos < MAX_E) g_col[pos] = s;
        }
    }
}

// ---------------- aggregation: one warp per node, mean of neighbor rows -------
__global__ void k_agg(const float* __restrict__ X, int layer) {
    int gw = (blockIdx.x * blockDim.x + threadIdx.x) >> 5;
    int lane = threadIdx.x & 31;
    if (gw >= N_NODES) return;
    int s = g_rowptr[gw];
    int n = g_deg[gw];
    const float4* Xv = (layer == 0) ? (const float4*)X : (const float4*)g_h;
    float4 acc = make_float4(0.f, 0.f, 0.f, 0.f);
    for (int j = s; j < s + n; j++) {
        int nb = g_col[j];
        float4 v = Xv[(size_t)nb * 32 + lane];
        acc.x += v.x; acc.y += v.y; acc.z += v.z; acc.w += v.w;
    }
    float inv = 1.0f / fmaxf((float)n, 1.0f);
    acc.x *= inv; acc.y *= inv; acc.z *= inv; acc.w *= inv;
    ((float4*)g_agg)[(size_t)gw * 32 + lane] = acc;
}

// ---------------- tf32 helpers ------------------------------------------------
__device__ __forceinline__ uint32_t f2tf32(float f) {
    uint32_t u;
    asm("cvt.rna.tf32.f32 %0, %1;" : "=r"(u) : "f"(f));
    return u;
}

__device__ __forceinline__ void mma_tf32(float d[4], const uint32_t a[4],
                                         uint32_t b0, uint32_t b1) {
    asm volatile(
        "mma.sync.aligned.m16n8k8.row.col.f32.tf32.tf32.f32 "
        "{%0,%1,%2,%3}, {%4,%5,%6,%7}, {%8,%9}, {%0,%1,%2,%3};\n"
        : "+f"(d[0]), "+f"(d[1]), "+f"(d[2]), "+f"(d[3])
        : "r"(a[0]), "r"(a[1]), "r"(a[2]), "r"(a[3]), "r"(b0), "r"(b1));
}

// ---------------- fused tf32 GEMM: out = [agg|self] @ [Wl;Wr] + b, l2norm ----
// block: 256 thr = 8 warps; block tile 128 rows x 128 cols; warp tile 32x64.
// K=256 in 8 chunks of 32. layer==0: self=X, dst=g_h, relu. layer==1: self=g_h,
// dst=OUT.
__global__ void __launch_bounds__(256)
k_gemm_mma(const float* __restrict__ X,
           const float* __restrict__ Wl, const float* __restrict__ Wr,
           const float* __restrict__ bb, float* __restrict__ OUT, int layer) {
    __shared__ uint32_t As[BM][36];    // [row][k] pad 36: banks 4*gid+tig
    __shared__ uint32_t Ws[32][136];   // [k][col] pad 136: banks 8*tig+gid
    __shared__ float RowS[2][BM];      // per-colgroup row sumsq

    int tid  = threadIdx.x;
    int warp = tid >> 5;
    int lane = tid & 31;
    int rg = warp >> 1;          // row group 0..3 (32 rows each)
    int cg = warp & 1;           // col group 0..1 (64 cols each)
    int gid = lane >> 2;         // 0..7
    int tig = lane & 3;          // 0..3
    int row0 = blockIdx.x * BM;

    const float* self = layer ? (const float*)g_h : X;
    float* dst = layer ? OUT : (float*)g_h;

    float acc[2][8][4];
#pragma unroll
    for (int m = 0; m < 2; m++)
#pragma unroll
        for (int n = 0; n < 8; n++)
#pragma unroll
            for (int j = 0; j < 4; j++) acc[m][n][j] = 0.f;

    for (int ch = 0; ch < 8; ch++) {
        // chunk ch<4 -> left operand (agg @ Wl); ch>=4 -> right (self @ Wr)
        const float* Asrc = (ch < 4) ? g_agg : self;
        const float* Wsrc = (ch < 4) ? Wl : Wr;
        int kcol = (ch & 3) * 32;   // column offset within the 128-wide source

        // load W chunk 32x128 (rows kcol..kcol+31 of Wsrc)
#pragma unroll
        for (int i = tid * 4; i < 32 * 128; i += 1024) {
            int kk = i >> 7, cc = i & 127;
            float4 v = *(const float4*)(Wsrc + (size_t)(kcol + kk) * 128 + cc);
            uint4 t = make_uint4(f2tf32(v.x), f2tf32(v.y), f2tf32(v.z), f2tf32(v.w));
            *(uint4*)&Ws[kk][cc] = t;
        }
        // load A chunk 128x32 (cols kcol..kcol+31 of Asrc)
#pragma unroll
        for (int i = tid * 4; i < 128 * 32; i += 1024) {
            int r = i >> 5, kk = i & 31;
            int grow = row0 + r;
            float4 v = make_float4(0.f, 0.f, 0.f, 0.f);
            if (grow < N_NODES)
                v = *(const float4*)(Asrc + (size_t)grow * 128 + kcol + kk);
            uint4 t = make_uint4(f2tf32(v.x), f2tf32(v.y), f2tf32(v.z), f2tf32(v.w));
            *(uint4*)&As[r][kk] = t;
        }
        __syncthreads();

#pragma unroll
        for (int ks = 0; ks < 4; ks++) {
            int kb = ks * 8;
            uint32_t a[2][4];
#pragma unroll
            for (int m = 0; m < 2; m++) {
                int r = rg * 32 + m * 16 + gid;
                a[m][0] = As[r][kb + tig];
                a[m][1] = As[r + 8][kb + tig];
                a[m][2] = As[r][kb + tig + 4];
                a[m][3] = As[r + 8][kb + tig + 4];
            }
#pragma unroll
            for (int n = 0; n < 8; n++) {
                int c = cg * 64 + n * 8 + gid;
                uint32_t b0 = Ws[kb + tig][c];
                uint32_t b1 = Ws[kb + tig + 4][c];
                mma_tf32(acc[0][n], a[0], b0, b1);
                mma_tf32(acc[1][n], a[1], b0, b1);
            }
        }
        __syncthreads();
    }

    // ---- epilogue: bias, row sum of squares, cross-colgroup reduce ----------
    float bv[8][2];
#pragma unroll
    for (int n = 0; n < 8; n++) {
        bv[n][0] = bb[cg * 64 + n * 8 + tig * 2];
        bv[n][1] = bb[cg * 64 + n * 8 + tig * 2 + 1];
    }

#pragma unroll
    for (int m = 0; m < 2; m++) {
        float s0 = 0.f, s1 = 0.f;
#pragma unroll
        for (int n = 0; n < 8; n++) {
            acc[m][n][0] += bv[n][0];
            acc[m][n][1] += bv[n][1];
            acc[m][n][2] += bv[n][0];
            acc[m][n][3] += bv[n][1];
            s0 = fmaf(acc[m][n][0], acc[m][n][0], s0);
            s0 = fmaf(acc[m][n][1], acc[m][n][1], s0);
            s1 = fmaf(acc[m][n][2], acc[m][n][2], s1);
            s1 = fmaf(acc[m][n][3], acc[m][n][3], s1);
        }
        s0 += __shfl_xor_sync(0xffffffffu, s0, 1);
        s0 += __shfl_xor_sync(0xffffffffu, s0, 2);
        s1 += __shfl_xor_sync(0xffffffffu, s1, 1);
        s1 += __shfl_xor_sync(0xffffffffu, s1, 2);
        if (tig == 0) {
            RowS[cg][rg * 32 + m * 16 + gid]     = s0;
            RowS[cg][rg * 32 + m * 16 + gid + 8] = s1;
        }
    }
    __syncthreads();

#pragma unroll
    for (int m = 0; m < 2; m++) {
        int rl = rg * 32 + m * 16 + gid;
        int rh = rl + 8;
        float inv0 = 1.0f / fmaxf(sqrtf(RowS[0][rl] + RowS[1][rl]), 1e-12f);
        float inv1 = 1.0f / fmaxf(sqrtf(RowS[0][rh] + RowS[1][rh]), 1e-12f);
        int glo = row0 + rl, ghi = row0 + rh;
        if (glo < N_NODES) {
            float* dp = dst + (size_t)glo * 128 + cg * 64 + tig * 2;
#pragma unroll
            for (int n = 0; n < 8; n++) {
                float o0 = acc[m][n][0] * inv0;
                float o1 = acc[m][n][1] * inv0;
                if (layer == 0) { o0 = fmaxf(o0, 0.f); o1 = fmaxf(o1, 0.f); }
                *(float2*)(dp + n * 8) = make_float2(o0, o1);
            }
        }
        if (ghi < N_NODES) {
            float* dp = dst + (size_t)ghi * 128 + cg * 64 + tig * 2;
#pragma unroll
            for (int n = 0; n < 8; n++) {
                float o0 = acc[m][n][2] * inv1;
                float o1 = acc[m][n][3] * inv1;
                if (layer == 0) { o0 = fmaxf(o0, 0.f); o1 = fmaxf(o1, 0.f); }
                *(float2*)(dp + n * 8) = make_float2(o0, o1);
            }
        }
    }
}

// ---------------- launch ------------------------------------------------------
extern "C" void kernel_launch(void* const* d_in, const int* in_sizes, int n_in,
                              void* d_out, int out_size) {
    const float* x   = (const float*)d_in[0];
    const void*  ei  = d_in[1];
    const float* W1l = (const float*)d_in[2];
    const float* b1  = (const float*)d_in[3];
    const float* W1r = (const float*)d_in[4];
    const float* W2l = (const float*)d_in[5];
    const float* b2  = (const float*)d_in[6];
    const float* W2r = (const float*)d_in[7];

    int E = in_sizes[1] / 2;
    float* out = (float*)d_out;

    int eb = (E + 255) / 256;
    int nb = (N_NODES + 255) / 256;

    // CSR build (per launch; deterministic work set)
    k_zero_deg<<<nb, 256>>>();
    k_probe<<<16, 256>>>(ei, E);
    k_hist<<<eb, 256>>>(ei, E);
    k_offsets<<<nb, 256>>>();
    k_fill<<<eb, 256>>>(ei, E);

    int aggBlocks  = (N_NODES * 32 + 255) / 256;
    int gemmBlocks = (N_NODES + BM - 1) / BM;

    // layer 1: agg(x) -> gemm -> g_h (normalize + relu)
    k_agg<<<aggBlocks, 256>>>(x, 0);
    k_gemm_mma<<<gemmBlocks, 256>>>(x, W1l, W1r, b1, out, 0);

    // layer 2: agg(g_h) -> gemm -> out (normalize)
    k_agg<<<aggBlocks, 256>>>(x, 1);
    k_gemm_mma<<<gemmBlocks, 256>>>(x, W2l, W2r, b2, out, 1);
}

// round 6
// speedup vs baseline: 3.4828x; 1.1962x over previous
#include <cuda_runtime.h>
#include <cuda_fp16.h>
#include <math.h>
#include <stdint.h>

#define N_NODES 100000
#define D 128
#define MAX_E 1600000
#define BM 128

// ---------------- scratch (static device globals; no runtime alloc) ----------
__device__ __align__(16) int    g_deg[N_NODES];
__device__ __align__(16) int    g_rowptr[N_NODES];
__device__ __align__(16) int    g_cursor[N_NODES];
__device__ __align__(16) int    g_col[MAX_E];
__device__ __align__(16) float  g_agg[(size_t)N_NODES * D];
__device__ __align__(16) __half g_x16[(size_t)N_NODES * D];
__device__ __align__(16) __half g_h16[(size_t)N_NODES * D];
__device__ int g_not64;   // 1 => edge_index is int32, 0 => int64
__device__ int g_total;   // segment allocator

// ---------------- dtype probe -------------------------------------------------
__global__ void k_probe(const void* __restrict__ ei, int E) {
    int i = blockIdx.x * blockDim.x + threadIdx.x;
    int n = E < 4096 ? E : 4096;
    if (i < n) {
        long long v = ((const long long*)ei)[i];
        if (v < 0 || v >= N_NODES) atomicExch(&g_not64, 1);
    }
}

// ---------------- CSR build ---------------------------------------------------
__global__ void k_zero_deg() {
    int i = blockIdx.x * blockDim.x + threadIdx.x;
    if (i < N_NODES) g_deg[i] = 0;
    if (i == 0) { g_not64 = 0; g_total = 0; }
}

__device__ __forceinline__ int load_idx(const void* ei, long long pos) {
    if (g_not64) return ((const int*)ei)[pos];
    return (int)((const long long*)ei)[pos];
}

__global__ void k_hist(const void* __restrict__ ei, int E) {
    int i = blockIdx.x * blockDim.x + threadIdx.x;
    if (i < E) {
        int d = load_idx(ei, (long long)E + i);   // dst row
        if ((unsigned)d < N_NODES) atomicAdd(&g_deg[d], 1);
    }
}

// segment offsets without a scan: order-free unique base per node
__global__ void k_offsets() {
    int i = blockIdx.x * blockDim.x + threadIdx.x;
    if (i < N_NODES) {
        int d = g_deg[i];
        int base = atomicAdd(&g_total, d);
        g_rowptr[i] = base;
        g_cursor[i] = base;
    }
}

__global__ void k_fill(const void* __restrict__ ei, int E) {
    int i = blockIdx.x * blockDim.x + threadIdx.x;
    if (i < E) {
        int d = load_idx(ei, (long long)E + i);
        int s = load_idx(ei, i);
        if ((unsigned)d < N_NODES && (unsigned)s < N_NODES) {
            int pos = atomicAdd(&g_cursor[d], 1);
            if (pos < MAX_E) g_col[pos] = s;
        }
    }
}

// ---------------- x -> fp16 copy ----------------------------------------------
__global__ void k_tohalf(const float* __restrict__ x) {
    int i = blockIdx.x * blockDim.x + threadIdx.x;   // float4 index
    const int total = N_NODES * D / 4;
    if (i < total) {
        float4 v = ((const float4*)x)[i];
        __half2 h0 = __floats2half2_rn(v.x, v.y);
        __half2 h1 = __floats2half2_rn(v.z, v.w);
        uint2 u;
        u.x = *(uint32_t*)&h0;
        u.y = *(uint32_t*)&h1;
        ((uint2*)g_x16)[i] = u;
    }
}

// ---------------- aggregation: one warp per node, fp16 gather, fp32 accum ----
template <int LAYER>
__global__ void k_agg(void) {
    int gw = (blockIdx.x * blockDim.x + threadIdx.x) >> 5;
    int lane = threadIdx.x & 31;
    if (gw >= N_NODES) return;
    int s = g_rowptr[gw];
    int n = g_deg[gw];
    const __half* src = (LAYER == 0) ? g_x16 : g_h16;
    const uint2* srcv = (const uint2*)src;   // 4 halves per lane
    float a0 = 0.f, a1 = 0.f, a2 = 0.f, a3 = 0.f;
    for (int j = s; j < s + n; j++) {
        int nb = g_col[j];
        uint2 u = srcv[(size_t)nb * 32 + lane];
        __half2 h0 = *(__half2*)&u.x;
        __half2 h1 = *(__half2*)&u.y;
        float2 f0 = __half22float2(h0);
        float2 f1 = __half22float2(h1);
        a0 += f0.x; a1 += f0.y; a2 += f1.x; a3 += f1.y;
    }
    float inv = 1.0f / fmaxf((float)n, 1.0f);
    float4 o = make_float4(a0 * inv, a1 * inv, a2 * inv, a3 * inv);
    ((float4*)g_agg)[(size_t)gw * 32 + lane] = o;
}

// ---------------- tf32 helpers ------------------------------------------------
__device__ __forceinline__ uint32_t f2tf32(float f) {
    uint32_t u;
    asm("cvt.rna.tf32.f32 %0, %1;" : "=r"(u) : "f"(f));
    return u;
}

__device__ __forceinline__ void mma_tf32(float d[4], const uint32_t a[4],
                                         uint32_t b0, uint32_t b1) {
    asm volatile(
        "mma.sync.aligned.m16n8k8.row.col.f32.tf32.tf32.f32 "
        "{%0,%1,%2,%3}, {%4,%5,%6,%7}, {%8,%9}, {%0,%1,%2,%3};\n"
        : "+f"(d[0]), "+f"(d[1]), "+f"(d[2]), "+f"(d[3])
        : "r"(a[0]), "r"(a[1]), "r"(a[2]), "r"(a[3]), "r"(b0), "r"(b1));
}

// ---------------- fused tf32 GEMM with register-prefetch pipeline -------------
// block: 256 thr = 8 warps; block tile 128 x 128; warp tile 32x64; K=256 in 8
// chunks of 32. LAYER 0: A=[g_agg|X], out -> g_h16 (relu). LAYER 1:
// A=[g_agg|g_h16], out -> OUT fp32.
template <int LAYER>
__global__ void __launch_bounds__(256)
k_gemm_mma(const float* __restrict__ X,
           const float* __restrict__ Wl, const float* __restrict__ Wr,
           const float* __restrict__ bb, float* __restrict__ OUT) {
    __shared__ uint32_t As[BM][36];    // [row][k] pad 36
    __shared__ uint32_t Ws[32][136];   // [k][col] pad 136
    __shared__ float RowS[2][BM];

    int tid  = threadIdx.x;
    int warp = tid >> 5;
    int lane = tid & 31;
    int rg = warp >> 1;
    int cg = warp & 1;
    int gid = lane >> 2;
    int tig = lane & 3;
    int row0 = blockIdx.x * BM;

    float wbuf[16], abuf[16];

    // chunk loader: ch<4 -> (g_agg, Wl); ch>=4 -> (self, Wr)
    auto ldg_chunk = [&](int ch) {
        const float* Wsrc = (ch < 4) ? Wl : Wr;
        int kcol = (ch & 3) * 32;
#pragma unroll
        for (int j = 0; j < 4; j++) {
            int i = tid * 4 + j * 1024;
            int kk = i >> 7, cc = i & 127;
            float4 v = *(const float4*)(Wsrc + (size_t)(kcol + kk) * 128 + cc);
            wbuf[j * 4 + 0] = v.x; wbuf[j * 4 + 1] = v.y;
            wbuf[j * 4 + 2] = v.z; wbuf[j * 4 + 3] = v.w;
        }
#pragma unroll
        for (int j = 0; j < 4; j++) {
            int i = tid * 4 + j * 1024;
            int r = i >> 5, kk = i & 31;
            int grow = row0 + r;
            float4 v = make_float4(0.f, 0.f, 0.f, 0.f);
            if (grow < N_NODES) {
                if (ch < 4) {
                    v = *(const float4*)(g_agg + (size_t)grow * 128 + kcol + kk);
                } else if (LAYER == 0) {
                    v = *(const float4*)(X + (size_t)grow * 128 + kcol + kk);
                } else {
                    uint2 u = *(const uint2*)(g_h16 + (size_t)grow * 128 + kcol + kk);
                    float2 f0 = __half22float2(*(__half2*)&u.x);
                    float2 f1 = __half22float2(*(__half2*)&u.y);
                    v = make_float4(f0.x, f0.y, f1.x, f1.y);
                }
            }
            abuf[j * 4 + 0] = v.x; abuf[j * 4 + 1] = v.y;
            abuf[j * 4 + 2] = v.z; abuf[j * 4 + 3] = v.w;
        }
    };

    float acc[2][8][4];
#pragma unroll
    for (int m = 0; m < 2; m++)
#pragma unroll
        for (int n = 0; n < 8; n++)
#pragma unroll
            for (int j = 0; j < 4; j++) acc[m][n][j] = 0.f;

    ldg_chunk(0);

    for (int ch = 0; ch < 8; ch++) {
        // store staged chunk to smem (tf32 convert here)
#pragma unroll
        for (int j = 0; j < 4; j++) {
            int i = tid * 4 + j * 1024;
            int kk = i >> 7, cc = i & 127;
            uint4 tw = make_uint4(f2tf32(wbuf[j * 4]), f2tf32(wbuf[j * 4 + 1]),
                                  f2tf32(wbuf[j * 4 + 2]), f2tf32(wbuf[j * 4 + 3]));
            *(uint4*)&Ws[kk][cc] = tw;
            int r = i >> 5, kk2 = i & 31;
            uint4 ta = make_uint4(f2tf32(abuf[j * 4]), f2tf32(abuf[j * 4 + 1]),
                                  f2tf32(abuf[j * 4 + 2]), f2tf32(abuf[j * 4 + 3]));
            *(uint4*)&As[r][kk2] = ta;
        }
        __syncthreads();

        if (ch < 7) ldg_chunk(ch + 1);   // prefetch overlaps the mma below

#pragma unroll
        for (int ks = 0; ks < 4; ks++) {
            int kb = ks * 8;
            uint32_t a[2][4];
#pragma unroll
            for (int m = 0; m < 2; m++) {
                int r = rg * 32 + m * 16 + gid;
                a[m][0] = As[r][kb + tig];
                a[m][1] = As[r + 8][kb + tig];
                a[m][2] = As[r][kb + tig + 4];
                a[m][3] = As[r + 8][kb + tig + 4];
            }
#pragma unroll
            for (int n = 0; n < 8; n++) {
                int c = cg * 64 + n * 8 + gid;
                uint32_t b0 = Ws[kb + tig][c];
                uint32_t b1 = Ws[kb + tig + 4][c];
                mma_tf32(acc[0][n], a[0], b0, b1);
                mma_tf32(acc[1][n], a[1], b0, b1);
            }
        }
        __syncthreads();
    }

    // ---- epilogue: bias, row sumsq, cross-colgroup reduce, normalize --------
    float bv[8][2];
#pragma unroll
    for (int n = 0; n < 8; n++) {
        bv[n][0] = bb[cg * 64 + n * 8 + tig * 2];
        bv[n][1] = bb[cg * 64 + n * 8 + tig * 2 + 1];
    }

#pragma unroll
    for (int m = 0; m < 2; m++) {
        float s0 = 0.f, s1 = 0.f;
#pragma unroll
        for (int n = 0; n < 8; n++) {
            acc[m][n][0] += bv[n][0];
            acc[m][n][1] += bv[n][1];
            acc[m][n][2] += bv[n][0];
            acc[m][n][3] += bv[n][1];
            s0 = fmaf(acc[m][n][0], acc[m][n][0], s0);
            s0 = fmaf(acc[m][n][1], acc[m][n][1], s0);
            s1 = fmaf(acc[m][n][2], acc[m][n][2], s1);
            s1 = fmaf(acc[m][n][3], acc[m][n][3], s1);
        }
        s0 += __shfl_xor_sync(0xffffffffu, s0, 1);
        s0 += __shfl_xor_sync(0xffffffffu, s0, 2);
        s1 += __shfl_xor_sync(0xffffffffu, s1, 1);
        s1 += __shfl_xor_sync(0xffffffffu, s1, 2);
        if (tig == 0) {
            RowS[cg][rg * 32 + m * 16 + gid]     = s0;
            RowS[cg][rg * 32 + m * 16 + gid + 8] = s1;
        }
    }
    __syncthreads();

#pragma unroll
    for (int m = 0; m < 2; m++) {
        int rl = rg * 32 + m * 16 + gid;
        int rh = rl + 8;
        float inv0 = 1.0f / fmaxf(sqrtf(RowS[0][rl] + RowS[1][rl]), 1e-12f);
        float inv1 = 1.0f / fmaxf(sqrtf(RowS[0][rh] + RowS[1][rh]), 1e-12f);
        int glo = row0 + rl, ghi = row0 + rh;
#pragma unroll
        for (int p = 0; p < 2; p++) {
            int grow = p ? ghi : glo;
            float inv = p ? inv1 : inv0;
            int o0i = p ? 2 : 0;
            if (grow >= N_NODES) continue;
            if (LAYER == 0) {
                __half* hp = g_h16 + (size_t)grow * 128 + cg * 64 + tig * 2;
#pragma unroll
                for (int n = 0; n < 8; n++) {
                    float o0 = fmaxf(acc[m][n][o0i] * inv, 0.f);
                    float o1 = fmaxf(acc[m][n][o0i + 1] * inv, 0.f);
                    *(__half2*)(hp + n * 8) = __floats2half2_rn(o0, o1);
                }
            } else {
                float* dp = OUT + (size_t)grow * 128 + cg * 64 + tig * 2;
#pragma unroll
                for (int n = 0; n < 8; n++) {
                    float o0 = acc[m][n][o0i] * inv;
                    float o1 = acc[m][n][o0i + 1] * inv;
                    *(float2*)(dp + n * 8) = make_float2(o0, o1);
                }
            }
        }
    }
}

// ---------------- launch ------------------------------------------------------
extern "C" void kernel_launch(void* const* d_in, const int* in_sizes, int n_in,
                              void* d_out, int out_size) {
    const float* x   = (const float*)d_in[0];
    const void*  ei  = d_in[1];
    const float* W1l = (const float*)d_in[2];
    const float* b1  = (const float*)d_in[3];
    const float* W1r = (const float*)d_in[4];
    const float* W2l = (const float*)d_in[5];
    const float* b2  = (const float*)d_in[6];
    const float* W2r = (const float*)d_in[7];

    int E = in_sizes[1] / 2;
    float* out = (float*)d_out;

    int eb = (E + 255) / 256;
    int nb = (N_NODES + 255) / 256;

    // CSR build + fp16 copy (per launch; deterministic work set)
    k_zero_deg<<<nb, 256>>>();
    k_probe<<<16, 256>>>(ei, E);
    k_hist<<<eb, 256>>>(ei, E);
    k_offsets<<<nb, 256>>>();
    k_fill<<<eb, 256>>>(ei, E);
    k_tohalf<<<(N_NODES * D / 4 + 255) / 256, 256>>>(x);

    int aggBlocks  = (N_NODES * 32 + 255) / 256;
    int gemmBlocks = (N_NODES + BM - 1) / BM;

    // layer 1: agg(x16) -> gemm -> g_h16 (normalize + relu)
    k_agg<0><<<aggBlocks, 256>>>();
    k_gemm_mma<0><<<gemmBlocks, 256>>>(x, W1l, W1r, b1, out);

    // layer 2: agg(g_h16) -> gemm -> out (normalize)
    k_agg<1><<<aggBlocks, 256>>>();
    k_gemm_mma<1><<<gemmBlocks, 256>>>(x, W2l, W2r, b2, out);
}

// round 7
// speedup vs baseline: 4.5925x; 1.3186x over previous
#include <cuda_runtime.h>
#include <cuda_fp16.h>
#include <math.h>
#include <stdint.h>

#define N_NODES 100000
#define D 128
#define MAX_E 1600000
#define BM 128

// ---------------- scratch (static device globals; no runtime alloc) ----------
__device__ __align__(16) int    g_deg[N_NODES];
__device__ __align__(16) int    g_rowptr[N_NODES];
__device__ __align__(16) int    g_cursor[N_NODES];
__device__ __align__(16) int    g_col[MAX_E];
__device__ __align__(16) __half g_agg16[(size_t)N_NODES * D];
__device__ __align__(16) __half g_x16[(size_t)N_NODES * D];
__device__ __align__(16) __half g_h16[(size_t)N_NODES * D];
__device__ int g_not64;   // 1 => edge_index is int32, 0 => int64
__device__ int g_total;   // segment allocator

// ---------------- dtype probe -------------------------------------------------
__global__ void k_probe(const void* __restrict__ ei, int E) {
    int i = blockIdx.x * blockDim.x + threadIdx.x;
    int n = E < 4096 ? E : 4096;
    if (i < n) {
        long long v = ((const long long*)ei)[i];
        if (v < 0 || v >= N_NODES) atomicExch(&g_not64, 1);
    }
}

// ---------------- CSR build ---------------------------------------------------
__global__ void k_zero_deg() {
    int i = blockIdx.x * blockDim.x + threadIdx.x;
    if (i < N_NODES) g_deg[i] = 0;
    if (i == 0) { g_not64 = 0; g_total = 0; }
}

__device__ __forceinline__ int load_idx(const void* ei, long long pos) {
    if (g_not64) return ((const int*)ei)[pos];
    return (int)((const long long*)ei)[pos];
}

__global__ void k_hist(const void* __restrict__ ei, int E) {
    int i = blockIdx.x * blockDim.x + threadIdx.x;
    if (i < E) {
        int d = load_idx(ei, (long long)E + i);   // dst row
        if ((unsigned)d < N_NODES) atomicAdd(&g_deg[d], 1);
    }
}

// warp-aggregated segment offsets: shfl-scan + one atomic per warp
__global__ void k_offsets() {
    int i = blockIdx.x * blockDim.x + threadIdx.x;
    int lane = threadIdx.x & 31;
    int d = (i < N_NODES) ? g_deg[i] : 0;
    int p = d;
#pragma unroll
    for (int off = 1; off < 32; off <<= 1) {
        int t = __shfl_up_sync(0xffffffffu, p, off);
        if (lane >= off) p += t;
    }
    int wsum = __shfl_sync(0xffffffffu, p, 31);
    int base = 0;
    if (lane == 31) base = atomicAdd(&g_total, wsum);
    base = __shfl_sync(0xffffffffu, base, 31);
    if (i < N_NODES) {
        int off = base + p - d;
        g_rowptr[i] = off;
        g_cursor[i] = off;
    }
}

__global__ void k_fill(const void* __restrict__ ei, int E) {
    int i = blockIdx.x * blockDim.x + threadIdx.x;
    if (i < E) {
        int d = load_idx(ei, (long long)E + i);
        int s = load_idx(ei, i);
        if ((unsigned)d < N_NODES && (unsigned)s < N_NODES) {
            int pos = atomicAdd(&g_cursor[d], 1);
            if (pos < MAX_E) g_col[pos] = s;
        }
    }
}

// ---------------- x -> fp16 copy ----------------------------------------------
__global__ void k_tohalf(const float* __restrict__ x) {
    int i = blockIdx.x * blockDim.x + threadIdx.x;   // float4 index
    const int total = N_NODES * D / 4;
    if (i < total) {
        float4 v = ((const float4*)x)[i];
        __half2 h0 = __floats2half2_rn(v.x, v.y);
        __half2 h1 = __floats2half2_rn(v.z, v.w);
        uint2 u;
        u.x = *(uint32_t*)&h0;
        u.y = *(uint32_t*)&h1;
        ((uint2*)g_x16)[i] = u;
    }
}

// ---------------- aggregation: warp/node, fp16 gather, fp32 accum, fp16 out --
template <int LAYER>
__global__ void k_agg(void) {
    int gw = (blockIdx.x * blockDim.x + threadIdx.x) >> 5;
    int lane = threadIdx.x & 31;
    if (gw >= N_NODES) return;
    int s = g_rowptr[gw];
    int n = g_deg[gw];
    const uint2* srcv = (LAYER == 0) ? (const uint2*)g_x16 : (const uint2*)g_h16;
    float a0 = 0.f, a1 = 0.f, a2 = 0.f, a3 = 0.f;
    int j = s;
    for (; j + 1 < s + n; j += 2) {
        int n0 = g_col[j], n1 = g_col[j + 1];
        uint2 u0 = srcv[(size_t)n0 * 32 + lane];
        uint2 u1 = srcv[(size_t)n1 * 32 + lane];
        float2 f;
        f = __half22float2(*(__half2*)&u0.x); a0 += f.x; a1 += f.y;
        f = __half22float2(*(__half2*)&u0.y); a2 += f.x; a3 += f.y;
        f = __half22float2(*(__half2*)&u1.x); a0 += f.x; a1 += f.y;
        f = __half22float2(*(__half2*)&u1.y); a2 += f.x; a3 += f.y;
    }
    if (j < s + n) {
        int n0 = g_col[j];
        uint2 u0 = srcv[(size_t)n0 * 32 + lane];
        float2 f;
        f = __half22float2(*(__half2*)&u0.x); a0 += f.x; a1 += f.y;
        f = __half22float2(*(__half2*)&u0.y); a2 += f.x; a3 += f.y;
    }
    float inv = 1.0f / fmaxf((float)n, 1.0f);
    __half2 h0 = __floats2half2_rn(a0 * inv, a1 * inv);
    __half2 h1 = __floats2half2_rn(a2 * inv, a3 * inv);
    uint2 o;
    o.x = *(uint32_t*)&h0;
    o.y = *(uint32_t*)&h1;
    ((uint2*)g_agg16)[(size_t)gw * 32 + lane] = o;
}

// ---------------- fp16 mma helper ---------------------------------------------
__device__ __forceinline__ void mma_f16(float d[4], uint32_t a0, uint32_t a1,
                                        uint32_t a2, uint32_t a3,
                                        uint32_t b0, uint32_t b1) {
    asm volatile(
        "mma.sync.aligned.m16n8k16.row.col.f32.f16.f16.f32 "
        "{%0,%1,%2,%3}, {%4,%5,%6,%7}, {%8,%9}, {%0,%1,%2,%3};\n"
        : "+f"(d[0]), "+f"(d[1]), "+f"(d[2]), "+f"(d[3])
        : "r"(a0), "r"(a1), "r"(a2), "r"(a3), "r"(b0), "r"(b1));
}

// ---------------- fused fp16 GEMM: out = [agg16|self16] @ [Wl;Wr] + b --------
// block 256 thr; tile 128x128; warp tile 32x64; K=256 in 8 chunks of 32.
// LAYER 0: self=g_x16, out -> g_h16 (relu). LAYER 1: self=g_h16, out fp32.
template <int LAYER>
__global__ void __launch_bounds__(256)
k_gemm_mma(const float* __restrict__ Wl, const float* __restrict__ Wr,
           const float* __restrict__ bb, float* __restrict__ OUT) {
    __shared__ __align__(16) __half As16[BM][40];   // [row][k] pad 40 halves
    __shared__ __align__(16) __half Ws16[32][136];  // [k][col] pad 136 halves
    __shared__ float RowS[2][BM];

    int tid  = threadIdx.x;
    int warp = tid >> 5;
    int lane = tid & 31;
    int rg = warp >> 1;
    int cg = warp & 1;
    int gid = lane >> 2;
    int tig = lane & 3;
    int row0 = blockIdx.x * BM;

    float4 wst[4];
    uint2  ast[4];

    auto ldg_chunk = [&](int ch) {
        const float*  Wsrc = (ch < 4) ? Wl : Wr;
        const __half* Asrc = (ch < 4) ? g_agg16
                                      : (LAYER == 0 ? g_x16 : g_h16);
        int kcol = (ch & 3) * 32;
#pragma unroll
        for (int j = 0; j < 4; j++) {
            int u = tid + j * 256;
            int kk = u >> 5, c = (u & 31) * 4;
            wst[j] = *(const float4*)(Wsrc + (size_t)(kcol + kk) * 128 + c);
            int r = (tid >> 3) + j * 32, kk2 = (tid & 7) * 4;
            int grow = row0 + r;
            uint2 v = make_uint2(0u, 0u);
            if (grow < N_NODES)
                v = *(const uint2*)(Asrc + (size_t)grow * 128 + kcol + kk2);
            ast[j] = v;
        }
    };

    float acc[2][8][4];
#pragma unroll
    for (int m = 0; m < 2; m++)
#pragma unroll
        for (int n = 0; n < 8; n++)
#pragma unroll
            for (int j = 0; j < 4; j++) acc[m][n][j] = 0.f;

    ldg_chunk(0);

    const uint32_t* As32 = (const uint32_t*)&As16[0][0];   // row stride 20 words

    for (int ch = 0; ch < 8; ch++) {
        // store staged chunk to smem (W converts fp32->fp16 here; A is raw copy)
#pragma unroll
        for (int j = 0; j < 4; j++) {
            int u = tid + j * 256;
            int kk = u >> 5, c = (u & 31) * 4;
            __half2 h0 = __floats2half2_rn(wst[j].x, wst[j].y);
            __half2 h1 = __floats2half2_rn(wst[j].z, wst[j].w);
            uint2 wv;
            wv.x = *(uint32_t*)&h0;
            wv.y = *(uint32_t*)&h1;
            *(uint2*)&Ws16[kk][c] = wv;
            int r = (tid >> 3) + j * 32, kk2 = (tid & 7) * 4;
            *(uint2*)&As16[r][kk2] = ast[j];
        }
        __syncthreads();

        if (ch < 7) ldg_chunk(ch + 1);   // prefetch overlaps mma below

#pragma unroll
        for (int ks = 0; ks < 2; ks++) {
            uint32_t a[2][4];
#pragma unroll
            for (int m = 0; m < 2; m++) {
                int r = rg * 32 + m * 16 + gid;
                a[m][0] = As32[r * 20 + ks * 8 + tig];
                a[m][1] = As32[(r + 8) * 20 + ks * 8 + tig];
                a[m][2] = As32[r * 20 + ks * 8 + tig + 4];
                a[m][3] = As32[(r + 8) * 20 + ks * 8 + tig + 4];
            }
#pragma unroll
            for (int np = 0; np < 4; np++) {
                int c0 = cg * 64 + np * 16;
                int krow = ks * 16 + (lane & 15);
                int ccol = c0 + (lane >> 4) * 8;
                uint32_t saddr =
                    (uint32_t)__cvta_generic_to_shared(&Ws16[krow][ccol]);
                uint32_t b0, b1, b2, b3;
                asm volatile(
                    "ldmatrix.sync.aligned.m8n8.x4.trans.shared.b16 "
                    "{%0,%1,%2,%3}, [%4];"
                    : "=r"(b0), "=r"(b1), "=r"(b2), "=r"(b3) : "r"(saddr));
                mma_f16(acc[0][2 * np],     a[0][0], a[0][1], a[0][2], a[0][3], b0, b1);
                mma_f16(acc[1][2 * np],     a[1][0], a[1][1], a[1][2], a[1][3], b0, b1);
                mma_f16(acc[0][2 * np + 1], a[0][0], a[0][1], a[0][2], a[0][3], b2, b3);
                mma_f16(acc[1][2 * np + 1], a[1][0], a[1][1], a[1][2], a[1][3], b2, b3);
            }
        }
        __syncthreads();
    }

    // ---- epilogue: bias, row sumsq, cross-colgroup reduce, normalize --------
    float bv[8][2];
#pragma unroll
    for (int n = 0; n < 8; n++) {
        bv[n][0] = bb[cg * 64 + n * 8 + tig * 2];
        bv[n][1] = bb[cg * 64 + n * 8 + tig * 2 + 1];
    }

#pragma unroll
    for (int m = 0; m < 2; m++) {
        float s0 = 0.f, s1 = 0.f;
#pragma unroll
        for (int n = 0; n < 8; n++) {
            acc[m][n][0] += bv[n][0];
            acc[m][n][1] += bv[n][1];
            acc[m][n][2] += bv[n][0];
            acc[m][n][3] += bv[n][1];
            s0 = fmaf(acc[m][n][0], acc[m][n][0], s0);
            s0 = fmaf(acc[m][n][1], acc[m][n][1], s0);
            s1 = fmaf(acc[m][n][2], acc[m][n][2], s1);
            s1 = fmaf(acc[m][n][3], acc[m][n][3], s1);
        }
        s0 += __shfl_xor_sync(0xffffffffu, s0, 1);
        s0 += __shfl_xor_sync(0xffffffffu, s0, 2);
        s1 += __shfl_xor_sync(0xffffffffu, s1, 1);
        s1 += __shfl_xor_sync(0xffffffffu, s1, 2);
        if (tig == 0) {
            RowS[cg][rg * 32 + m * 16 + gid]     = s0;
            RowS[cg][rg * 32 + m * 16 + gid + 8] = s1;
        }
    }
    __syncthreads();

#pragma unroll
    for (int m = 0; m < 2; m++) {
        int rl = rg * 32 + m * 16 + gid;
        int rh = rl + 8;
        float inv0 = 1.0f / fmaxf(sqrtf(RowS[0][rl] + RowS[1][rl]), 1e-12f);
        float inv1 = 1.0f / fmaxf(sqrtf(RowS[0][rh] + RowS[1][rh]), 1e-12f);
        int glo = row0 + rl, ghi = row0 + rh;
#pragma unroll
        for (int p = 0; p < 2; p++) {
            int grow = p ? ghi : glo;
            float inv = p ? inv1 : inv0;
            int o0i = p ? 2 : 0;
            if (grow >= N_NODES) continue;
            if (LAYER == 0) {
                __half* hp = g_h16 + (size_t)grow * 128 + cg * 64 + tig * 2;
#pragma unroll
                for (int n = 0; n < 8; n++) {
                    float o0 = fmaxf(acc[m][n][o0i] * inv, 0.f);
                    float o1 = fmaxf(acc[m][n][o0i + 1] * inv, 0.f);
                    *(__half2*)(hp + n * 8) = __floats2half2_rn(o0, o1);
                }
            } else {
                float* dp = OUT + (size_t)grow * 128 + cg * 64 + tig * 2;
#pragma unroll
                for (int n = 0; n < 8; n++) {
                    float o0 = acc[m][n][o0i] * inv;
                    float o1 = acc[m][n][o0i + 1] * inv;
                    *(float2*)(dp + n * 8) = make_float2(o0, o1);
                }
            }
        }
    }
}

// ---------------- launch ------------------------------------------------------
extern "C" void kernel_launch(void* const* d_in, const int* in_sizes, int n_in,
                              void* d_out, int out_size) {
    const float* x   = (const float*)d_in[0];
    const void*  ei  = d_in[1];
    const float* W1l = (const float*)d_in[2];
    const float* b1  = (const float*)d_in[3];
    const float* W1r = (const float*)d_in[4];
    const float* W2l = (const float*)d_in[5];
    const float* b2  = (const float*)d_in[6];
    const float* W2r = (const float*)d_in[7];

    int E = in_sizes[1] / 2;
    float* out = (float*)d_out;

    int eb = (E + 255) / 256;
    int nb = (N_NODES + 255) / 256;

    // CSR build + fp16 copy (per launch; deterministic work set)
    k_zero_deg<<<nb, 256>>>();
    k_probe<<<16, 256>>>(ei, E);
    k_hist<<<eb, 256>>>(ei, E);
    k_offsets<<<nb, 256>>>();
    k_fill<<<eb, 256>>>(ei, E);
    k_tohalf<<<(N_NODES * D / 4 + 255) / 256, 256>>>(x);

    int aggBlocks  = (N_NODES * 32 + 255) / 256;
    int gemmBlocks = (N_NODES + BM - 1) / BM;

    // layer 1: agg(x16) -> gemm -> g_h16 (normalize + relu)
    k_agg<0><<<aggBlocks, 256>>>();
    k_gemm_mma<0><<<gemmBlocks, 256>>>(W1l, W1r, b1, out);

    // layer 2: agg(g_h16) -> gemm -> out (normalize)
    k_agg<1><<<aggBlocks, 256>>>();
    k_gemm_mma<1><<<gemmBlocks, 256>>>(W2l, W2r, b2, out);
}

// round 8
// speedup vs baseline: 4.6951x; 1.0224x over previous
#include <cuda_runtime.h>
#include <cuda_fp16.h>
#include <stdint.h>

#define N_NODES 100000
#define D 128
#define MAX_E 1600000
#define BM 128

// ---------------- scratch (static device globals; no runtime alloc) ----------
__device__ __align__(16) int    g_deg[N_NODES];
__device__ __align__(16) int    g_rowptr[N_NODES];
__device__ __align__(16) int    g_cursor[N_NODES];
__device__ __align__(16) int    g_col[MAX_E];
__device__ __align__(16) __half g_agg16[(size_t)N_NODES * D];
__device__ __align__(16) __half g_x16[(size_t)N_NODES * D];
__device__ __align__(16) __half g_h16[(size_t)N_NODES * D];
__device__ __align__(16) __half g_w16[4 * 128 * 128];   // [W1l|W1r|W2l|W2r] fp16
__device__ int g_not64;   // 1 => edge_index is int32, 0 => int64
__device__ int g_total;   // segment allocator

// ---------------- flag zero (must precede k_prep's probe) --------------------
__global__ void k_zero2() {
    if (threadIdx.x == 0) { g_not64 = 0; g_total = 0; }
}

// ---------------- fused prologue: tohalf | zero_deg | probe | W->fp16 --------
#define NB_X 12500          // N_NODES*D/4 float4s / 256
#define NB_Z 391
#define NB_P 16
#define NB_W 64             // 4*128*128 floats / 4 / 256

__global__ void k_prep(const float* __restrict__ x, const void* __restrict__ ei,
                       const float* __restrict__ W1l, const float* __restrict__ W1r,
                       const float* __restrict__ W2l, const float* __restrict__ W2r,
                       int E) {
    int b = blockIdx.x;
    int t = threadIdx.x;
    if (b < NB_X) {                              // x -> fp16
        int i = b * 256 + t;
        float4 v = ((const float4*)x)[i];
        __half2 h0 = __floats2half2_rn(v.x, v.y);
        __half2 h1 = __floats2half2_rn(v.z, v.w);
        uint2 u;
        u.x = *(uint32_t*)&h0;
        u.y = *(uint32_t*)&h1;
        ((uint2*)g_x16)[i] = u;
    } else if (b < NB_X + NB_Z) {                // zero degree
        int i = (b - NB_X) * 256 + t;
        if (i < N_NODES) g_deg[i] = 0;
    } else if (b < NB_X + NB_Z + NB_P) {         // dtype probe
        int i = (b - NB_X - NB_Z) * 256 + t;
        int n = E < 4096 ? E : 4096;
        if (i < n) {
            long long v = ((const long long*)ei)[i];
            if (v < 0 || v >= N_NODES) atomicExch(&g_not64, 1);
        }
    } else {                                     // W -> fp16
        int i = (b - NB_X - NB_Z - NB_P) * 256 + t;   // float4 index 0..16383
        const float* s = (i < 4096) ? W1l : (i < 8192) ? W1r
                        : (i < 12288) ? W2l : W2r;
        float4 v = ((const float4*)s)[i & 4095];
        __half2 h0 = __floats2half2_rn(v.x, v.y);
        __half2 h1 = __floats2half2_rn(v.z, v.w);
        uint2 u;
        u.x = *(uint32_t*)&h0;
        u.y = *(uint32_t*)&h1;
        ((uint2*)g_w16)[i] = u;
    }
}

// ---------------- CSR build ---------------------------------------------------
__device__ __forceinline__ int load_idx(const void* ei, long long pos) {
    if (g_not64) return ((const int*)ei)[pos];
    return (int)((const long long*)ei)[pos];
}

__global__ void k_hist(const void* __restrict__ ei, int E) {
    int i = (blockIdx.x * blockDim.x + threadIdx.x) * 2;
    if (i < E) {
        int d = load_idx(ei, (long long)E + i);
        if ((unsigned)d < N_NODES) atomicAdd(&g_deg[d], 1);
    }
    if (i + 1 < E) {
        int d = load_idx(ei, (long long)E + i + 1);
        if ((unsigned)d < N_NODES) atomicAdd(&g_deg[d], 1);
    }
}

// block-aggregated segment offsets: shfl-scan + smem warp scan + 1 atomic/block
__global__ void k_offsets() {
    __shared__ int wsum[8];
    __shared__ int bbase;
    int i = blockIdx.x * blockDim.x + threadIdx.x;
    int lane = threadIdx.x & 31;
    int wid = threadIdx.x >> 5;
    int d = (i < N_NODES) ? g_deg[i] : 0;
    int p = d;
#pragma unroll
    for (int off = 1; off < 32; off <<= 1) {
        int t = __shfl_up_sync(0xffffffffu, p, off);
        if (lane >= off) p += t;
    }
    if (lane == 31) wsum[wid] = p;
    __syncthreads();
    if (threadIdx.x == 0) {
        int tot = 0;
#pragma unroll
        for (int w = 0; w < 8; w++) { int t = wsum[w]; wsum[w] = tot; tot += t; }
        bbase = atomicAdd(&g_total, tot);
    }
    __syncthreads();
    if (i < N_NODES) {
        int off = bbase + wsum[wid] + p - d;
        g_rowptr[i] = off;
        g_cursor[i] = off;
    }
}

__global__ void k_fill(const void* __restrict__ ei, int E) {
    int i = (blockIdx.x * blockDim.x + threadIdx.x) * 2;
#pragma unroll
    for (int q = 0; q < 2; q++) {
        int e = i + q;
        if (e < E) {
            int d = load_idx(ei, (long long)E + e);
            int s = load_idx(ei, e);
            if ((unsigned)d < N_NODES && (unsigned)s < N_NODES) {
                int pos = atomicAdd(&g_cursor[d], 1);
                if (pos < MAX_E) g_col[pos] = s;
            }
        }
    }
}

// ---------------- aggregation: warp/node, half-warp x 2 edges, 16B lanes -----
template <int LAYER>
__global__ void k_agg(void) {
    int gw = (blockIdx.x * blockDim.x + threadIdx.x) >> 5;
    int lane = threadIdx.x & 31;
    if (gw >= N_NODES) return;
    int s = g_rowptr[gw];
    int n = g_deg[gw];
    int half = lane >> 4;
    int sub = lane & 15;
    const uint4* src = (LAYER == 0) ? (const uint4*)g_x16 : (const uint4*)g_h16;
    float a[8];
#pragma unroll
    for (int q = 0; q < 8; q++) a[q] = 0.f;

    int j = s + half;
    int end = s + n;
    // 2x unroll over this half-warp's edges (stride 2 each)
    for (; j + 2 < end; j += 4) {
        int n0 = g_col[j], n1 = g_col[j + 2];
        uint4 u0 = src[(size_t)n0 * 16 + sub];
        uint4 u1 = src[(size_t)n1 * 16 + sub];
        float2 f;
        f = __half22float2(*(__half2*)&u0.x); a[0] += f.x; a[1] += f.y;
        f = __half22float2(*(__half2*)&u0.y); a[2] += f.x; a[3] += f.y;
        f = __half22float2(*(__half2*)&u0.z); a[4] += f.x; a[5] += f.y;
        f = __half22float2(*(__half2*)&u0.w); a[6] += f.x; a[7] += f.y;
        f = __half22float2(*(__half2*)&u1.x); a[0] += f.x; a[1] += f.y;
        f = __half22float2(*(__half2*)&u1.y); a[2] += f.x; a[3] += f.y;
        f = __half22float2(*(__half2*)&u1.z); a[4] += f.x; a[5] += f.y;
        f = __half22float2(*(__half2*)&u1.w); a[6] += f.x; a[7] += f.y;
    }
    for (; j < end; j += 2) {
        int n0 = g_col[j];
        uint4 u0 = src[(size_t)n0 * 16 + sub];
        float2 f;
        f = __half22float2(*(__half2*)&u0.x); a[0] += f.x; a[1] += f.y;
        f = __half22float2(*(__half2*)&u0.y); a[2] += f.x; a[3] += f.y;
        f = __half22float2(*(__half2*)&u0.z); a[4] += f.x; a[5] += f.y;
        f = __half22float2(*(__half2*)&u0.w); a[6] += f.x; a[7] += f.y;
    }
    // combine the two half-warps
#pragma unroll
    for (int q = 0; q < 8; q++)
        a[q] += __shfl_down_sync(0xffffffffu, a[q], 16);
    if (half == 0) {
        float inv = 1.0f / fmaxf((float)n, 1.0f);
        __half2 h0 = __floats2half2_rn(a[0] * inv, a[1] * inv);
        __half2 h1 = __floats2half2_rn(a[2] * inv, a[3] * inv);
        __half2 h2 = __floats2half2_rn(a[4] * inv, a[5] * inv);
        __half2 h3 = __floats2half2_rn(a[6] * inv, a[7] * inv);
        uint4 o;
        o.x = *(uint32_t*)&h0;
        o.y = *(uint32_t*)&h1;
        o.z = *(uint32_t*)&h2;
        o.w = *(uint32_t*)&h3;
        ((uint4*)g_agg16)[(size_t)gw * 16 + sub] = o;
    }
}

// ---------------- fp16 mma helper ---------------------------------------------
__device__ __forceinline__ void mma_f16(float d[4], uint32_t a0, uint32_t a1,
                                        uint32_t a2, uint32_t a3,
                                        uint32_t b0, uint32_t b1) {
    asm volatile(
        "mma.sync.aligned.m16n8k16.row.col.f32.f16.f16.f32 "
        "{%0,%1,%2,%3}, {%4,%5,%6,%7}, {%8,%9}, {%0,%1,%2,%3};\n"
        : "+f"(d[0]), "+f"(d[1]), "+f"(d[2]), "+f"(d[3])
        : "r"(a0), "r"(a1), "r"(a2), "r"(a3), "r"(b0), "r"(b1));
}

// ---------------- fused fp16 GEMM, double-buffered smem ----------------------
// block 256 thr; tile 128x128; warp tile 32x64; K=256 in 8 chunks of 32.
// LAYER 0: A=[agg16|x16], out -> g_h16 (relu). LAYER 1: A=[agg16|h16], out fp32.
template <int LAYER>
__global__ void __launch_bounds__(256)
k_gemm_mma(const float* __restrict__ bb, float* __restrict__ OUT) {
    __shared__ __align__(16) __half As16[2][BM][40];   // [buf][row][k]
    __shared__ __align__(16) __half Ws16[2][32][136];  // [buf][k][col]
    __shared__ float RowS[2][BM];

    int tid  = threadIdx.x;
    int warp = tid >> 5;
    int lane = tid & 31;
    int rg = warp >> 1;
    int cg = warp & 1;
    int gid = lane >> 2;
    int tig = lane & 3;
    int row0 = blockIdx.x * BM;

    const __half* Wbase = g_w16 + LAYER * 32768;
    uint2 wst[4], ast[4];

    auto ldg_chunk = [&](int ch) {
        const __half* Wsrc = Wbase + (ch < 4 ? 0 : 16384);
        const __half* Asrc = (ch < 4) ? g_agg16 : (LAYER == 0 ? g_x16 : g_h16);
        int kcol = (ch & 3) * 32;
#pragma unroll
        for (int j = 0; j < 4; j++) {
            int u = tid + j * 256;
            int kk = u >> 5, c = (u & 31) * 4;
            wst[j] = *(const uint2*)(Wsrc + (size_t)(kcol + kk) * 128 + c);
            int r = (tid >> 3) + j * 32, kk2 = (tid & 7) * 4;
            int grow = row0 + r;
            uint2 v = make_uint2(0u, 0u);
            if (grow < N_NODES)
                v = *(const uint2*)(Asrc + (size_t)grow * 128 + kcol + kk2);
            ast[j] = v;
        }
    };
    auto st_chunk = [&](int buf) {
#pragma unroll
        for (int j = 0; j < 4; j++) {
            int u = tid + j * 256;
            int kk = u >> 5, c = (u & 31) * 4;
            *(uint2*)&Ws16[buf][kk][c] = wst[j];
            int r = (tid >> 3) + j * 32, kk2 = (tid & 7) * 4;
            *(uint2*)&As16[buf][r][kk2] = ast[j];
        }
    };

    float acc[2][8][4];
#pragma unroll
    for (int m = 0; m < 2; m++)
#pragma unroll
        for (int n = 0; n < 8; n++)
#pragma unroll
            for (int j = 0; j < 4; j++) acc[m][n][j] = 0.f;

    ldg_chunk(0);
    st_chunk(0);

    for (int ch = 0; ch < 8; ch++) {
        __syncthreads();                     // buf[ch&1] visible to all
        if (ch < 7) ldg_chunk(ch + 1);       // overlaps mma below
        int buf = ch & 1;
        const uint32_t* As32 = (const uint32_t*)&As16[buf][0][0];  // stride 20

#pragma unroll
        for (int ks = 0; ks < 2; ks++) {
            uint32_t a[2][4];
#pragma unroll
            for (int m = 0; m < 2; m++) {
                int r = rg * 32 + m * 16 + gid;
                a[m][0] = As32[r * 20 + ks * 8 + tig];
                a[m][1] = As32[(r + 8) * 20 + ks * 8 + tig];
                a[m][2] = As32[r * 20 + ks * 8 + tig + 4];
                a[m][3] = As32[(r + 8) * 20 + ks * 8 + tig + 4];
            }
#pragma unroll
            for (int np = 0; np < 4; np++) {
                int c0 = cg * 64 + np * 16;
                int krow = ks * 16 + (lane & 15);
                int ccol = c0 + (lane >> 4) * 8;
                uint32_t saddr =
                    (uint32_t)__cvta_generic_to_shared(&Ws16[buf][krow][ccol]);
                uint32_t b0, b1, b2, b3;
                asm volatile(
                    "ldmatrix.sync.aligned.m8n8.x4.trans.shared.b16 "
                    "{%0,%1,%2,%3}, [%4];"
                    : "=r"(b0), "=r"(b1), "=r"(b2), "=r"(b3) : "r"(saddr));
                mma_f16(acc[0][2 * np],     a[0][0], a[0][1], a[0][2], a[0][3], b0, b1);
                mma_f16(acc[1][2 * np],     a[1][0], a[1][1], a[1][2], a[1][3], b0, b1);
                mma_f16(acc[0][2 * np + 1], a[0][0], a[0][1], a[0][2], a[0][3], b2, b3);
                mma_f16(acc[1][2 * np + 1], a[1][0], a[1][1], a[1][2], a[1][3], b2, b3);
            }
        }
        if (ch < 7) st_chunk((ch + 1) & 1);  // write other buffer; sync'd next iter
    }
    __syncthreads();

    // ---- epilogue: bias, row sumsq, cross-colgroup reduce, normalize --------
    float bv[8][2];
#pragma unroll
    for (int n = 0; n < 8; n++) {
        bv[n][0] = bb[cg * 64 + n * 8 + tig * 2];
        bv[n][1] = bb[cg * 64 + n * 8 + tig * 2 + 1];
    }

#pragma unroll
    for (int m = 0; m < 2; m++) {
        float s0 = 0.f, s1 = 0.f;
#pragma unroll
        for (int n = 0; n < 8; n++) {
            acc[m][n][0] += bv[n][0];
            acc[m][n][1] += bv[n][1];
            acc[m][n][2] += bv[n][0];
            acc[m][n][3] += bv[n][1];
            s0 = fmaf(acc[m][n][0], acc[m][n][0], s0);
            s0 = fmaf(acc[m][n][1], acc[m][n][1], s0);
            s1 = fmaf(acc[m][n][2], acc[m][n][2], s1);
            s1 = fmaf(acc[m][n][3], acc[m][n][3], s1);
        }
        s0 += __shfl_xor_sync(0xffffffffu, s0, 1);
        s0 += __shfl_xor_sync(0xffffffffu, s0, 2);
        s1 += __shfl_xor_sync(0xffffffffu, s1, 1);
        s1 += __shfl_xor_sync(0xffffffffu, s1, 2);
        if (tig == 0) {
            RowS[cg][rg * 32 + m * 16 + gid]     = s0;
            RowS[cg][rg * 32 + m * 16 + gid + 8] = s1;
        }
    }
    __syncthreads();

#pragma unroll
    for (int m = 0; m < 2; m++) {
        int rl = rg * 32 + m * 16 + gid;
        int rh = rl + 8;
        float inv0 = 1.0f / fmaxf(sqrtf(RowS[0][rl] + RowS[1][rl]), 1e-12f);
        float inv1 = 1.0f / fmaxf(sqrtf(RowS[0][rh] + RowS[1][rh]), 1e-12f);
        int glo = row0 + rl, ghi = row0 + rh;
#pragma unroll
        for (int p = 0; p < 2; p++) {
            int grow = p ? ghi : glo;
            float inv = p ? inv1 : inv0;
            int o0i = p ? 2 : 0;
            if (grow >= N_NODES) continue;
            if (LAYER == 0) {
                __half* hp = g_h16 + (size_t)grow * 128 + cg * 64 + tig * 2;
#pragma unroll
                for (int n = 0; n < 8; n++) {
                    float o0 = fmaxf(acc[m][n][o0i] * inv, 0.f);
                    float o1 = fmaxf(acc[m][n][o0i + 1] * inv, 0.f);
                    *(__half2*)(hp + n * 8) = __floats2half2_rn(o0, o1);
                }
            } else {
                float* dp = OUT + (size_t)grow * 128 + cg * 64 + tig * 2;
#pragma unroll
                for (int n = 0; n < 8; n++) {
                    float o0 = acc[m][n][o0i] * inv;
                    float o1 = acc[m][n][o0i + 1] * inv;
                    *(float2*)(dp + n * 8) = make_float2(o0, o1);
                }
            }
        }
    }
}

// ---------------- launch ------------------------------------------------------
extern "C" void kernel_launch(void* const* d_in, const int* in_sizes, int n_in,
                              void* d_out, int out_size) {
    const float* x   = (const float*)d_in[0];
    const void*  ei  = d_in[1];
    const float* W1l = (const float*)d_in[2];
    const float* b1  = (const float*)d_in[3];
    const float* W1r = (const float*)d_in[4];
    const float* W2l = (const float*)d_in[5];
    const float* b2  = (const float*)d_in[6];
    const float* W2r = (const float*)d_in[7];

    int E = in_sizes[1] / 2;
    float* out = (float*)d_out;

    int eb2 = (E / 2 + 255) / 256;
    int nb = (N_NODES + 255) / 256;

    k_zero2<<<1, 32>>>();
    k_prep<<<NB_X + NB_Z + NB_P + NB_W, 256>>>(x, ei, W1l, W1r, W2l, W2r, E);
    k_hist<<<eb2, 256>>>(ei, E);
    k_offsets<<<nb, 256>>>();
    k_fill<<<eb2, 256>>>(ei, E);

    int aggBlocks  = (N_NODES * 32 + 255) / 256;
    int gemmBlocks = (N_NODES + BM - 1) / BM;

    // layer 1: agg(x16) -> gemm -> g_h16 (normalize + relu)
    k_agg<0><<<aggBlocks, 256>>>();
    k_gemm_mma<0><<<gemmBlocks, 256>>>(b1, out);

    // layer 2: agg(g_h16) -> gemm -> out (normalize)
    k_agg<1><<<aggBlocks, 256>>>();
    k_gemm_mma<1><<<gemmBlocks, 256>>>(b2, out);
}